// round 5
// baseline (speedup 1.0000x reference)
#include <cuda_runtime.h>
#include <math_constants.h>
#include <math.h>

// Problem constants (shapes fixed by setup_inputs)
#define IMG_H 512
#define IMG_W 512
#define HW (IMG_H * IMG_W)
#define BATCH 8
#define NSLICE 16          // slices 0..7 = pred prob, 8..15 = y_true as float
#define NUM_ITER 40

// Scratch (static device globals — no allocation)
__device__ float  g_imgA[NSLICE * HW];
__device__ float  g_imgB[NSLICE * HW];
__device__ float  g_skel[NSLICE * HW];
// g_acc layout: [slice*3 + {sum_ep, sum_ep*y, sum_ep*x}] for slice 0..15 (48 doubles),
//               [48]=dice inter, [49]=sum_pred, [50]=sum_true
__device__ double g_acc[64];

// ---------------------------------------------------------------------------
__global__ void zero_acc_kernel() {
    if (threadIdx.x < 64) g_acc[threadIdx.x] = 0.0;
}

// ---------------------------------------------------------------------------
// Init: pred prob = softmax fg = 1/(1+exp(x0-x1)); slices 8..15 = float(y_true).
// Also accumulates the dice sums (inter, sum_pred, sum_true).
__global__ void __launch_bounds__(256) init_kernel(const float* __restrict__ net,
                                                   const int* __restrict__ ytrue) {
    double inter = 0.0, sp = 0.0, st = 0.0;
    const int total = BATCH * HW;
    for (int idx = blockIdx.x * blockDim.x + threadIdx.x; idx < total;
         idx += gridDim.x * blockDim.x) {
        int b = idx / HW;
        int p = idx - b * HW;
        float x0 = net[(b * 2 + 0) * HW + p];
        float x1 = net[(b * 2 + 1) * HW + p];
        float pr = 1.0f / (1.0f + expf(x0 - x1));
        float tv = (float)ytrue[idx];
        g_imgA[idx] = pr;
        g_imgA[BATCH * HW + idx] = tv;
        inter += (double)(tv * pr);
        sp += (double)pr;
        st += (double)tv;
    }
    // block reduction (256 threads = 8 warps)
    __shared__ double red[8][3];
    unsigned lane = threadIdx.x & 31u, wid = threadIdx.x >> 5;
    #pragma unroll
    for (int o = 16; o > 0; o >>= 1) {
        inter += __shfl_down_sync(0xffffffffu, inter, o);
        sp    += __shfl_down_sync(0xffffffffu, sp, o);
        st    += __shfl_down_sync(0xffffffffu, st, o);
    }
    if (lane == 0) { red[wid][0] = inter; red[wid][1] = sp; red[wid][2] = st; }
    __syncthreads();
    if (wid == 0) {
        inter = (lane < 8) ? red[lane][0] : 0.0;
        sp    = (lane < 8) ? red[lane][1] : 0.0;
        st    = (lane < 8) ? red[lane][2] : 0.0;
        #pragma unroll
        for (int o = 4; o > 0; o >>= 1) {
            inter += __shfl_down_sync(0xffffffffu, inter, o);
            sp    += __shfl_down_sync(0xffffffffu, sp, o);
            st    += __shfl_down_sync(0xffffffffu, st, o);
        }
        if (lane == 0) {
            atomicAdd(&g_acc[48], inter);
            atomicAdd(&g_acc[49], sp);
            atomicAdd(&g_acc[50], st);
        }
    }
}

// ---------------------------------------------------------------------------
// One soft_skel iteration fused into a single kernel.
// ERODE=true:  new_img = erode(img); open = dilate(erode(new_img));
// ERODE=false: new_img = img (first call, initial skel only; img not rewritten)
// INIT=true:   skel = relu(new_img - open)
// INIT=false:  skel += relu(delta - skel*delta), delta = relu(new_img - open)
// erode = min over 5-point cross (inf padding), dilate = 3x3 max (-inf padding)
template <bool ERODE, bool INIT>
__global__ void __launch_bounds__(1024) morph_kernel(int inA) {
    const float* __restrict__ img_in  = inA ? g_imgA : g_imgB;
    float* __restrict__       img_out = inA ? g_imgB : g_imgA;

    __shared__ float s_img[38][40];
    __shared__ float s_e1[36][40];
    __shared__ float s_e2[34][40];

    const int slice = blockIdx.z;
    const int gx0 = blockIdx.x * 32;
    const int gy0 = blockIdx.y * 32;
    const int t = threadIdx.y * 32 + threadIdx.x;
    const float INF = CUDART_INF_F;
    const float* base = img_in + slice * HW;

    // Load 38x38 halo (OOB -> +inf : matches min-pool inf padding)
    for (int idx = t; idx < 38 * 38; idx += 1024) {
        int j = idx / 38, i = idx - j * 38;
        int gy = gy0 + j - 3, gx = gx0 + i - 3;
        float v = INF;
        if ((unsigned)gy < IMG_H && (unsigned)gx < IMG_W)
            v = __ldg(base + gy * IMG_W + gx);
        s_img[j][i] = v;
    }
    __syncthreads();

    // Stage 1: e1 on 36x36 region (output +-2). OOB positions forced +inf
    // (they feed the next erode/min).
    for (int idx = t; idx < 36 * 36; idx += 1024) {
        int j = idx / 36, i = idx - j * 36;
        int gy = gy0 + j - 2, gx = gx0 + i - 2;
        float v = INF;
        if ((unsigned)gy < IMG_H && (unsigned)gx < IMG_W) {
            float c = s_img[j + 1][i + 1];
            if (ERODE) {
                float vv = fminf(s_img[j][i + 1], s_img[j + 2][i + 1]);
                float hh = fminf(s_img[j + 1][i], s_img[j + 1][i + 2]);
                v = fminf(c, fminf(vv, hh));
            } else {
                v = c;
            }
        }
        s_e1[j][i] = v;
    }
    __syncthreads();

    // Stage 2: e2 = erode(e1) on 34x34 region (output +-1). OOB positions
    // forced -inf (they feed the dilate/max).
    for (int idx = t; idx < 34 * 34; idx += 1024) {
        int j = idx / 34, i = idx - j * 34;
        int gy = gy0 + j - 1, gx = gx0 + i - 1;
        float v = -INF;
        if ((unsigned)gy < IMG_H && (unsigned)gx < IMG_W) {
            float c = s_e1[j + 1][i + 1];
            float vv = fminf(s_e1[j][i + 1], s_e1[j + 2][i + 1]);
            float hh = fminf(s_e1[j + 1][i], s_e1[j + 1][i + 2]);
            v = fminf(c, fminf(vv, hh));
        }
        s_e2[j][i] = v;
    }
    __syncthreads();

    // Stage 3: open = 3x3 max of e2; delta; skel update; write new img.
    const int ty = threadIdx.y, tx = threadIdx.x;
    float open = -INF;
    #pragma unroll
    for (int dj = 0; dj < 3; dj++)
        #pragma unroll
        for (int di = 0; di < 3; di++)
            open = fmaxf(open, s_e2[ty + dj][tx + di]);

    float nv = s_e1[ty + 2][tx + 2];
    float delta = fmaxf(nv - open, 0.0f);
    int gp = slice * HW + (gy0 + ty) * IMG_W + (gx0 + tx);
    if (ERODE) img_out[gp] = nv;
    if (INIT) {
        g_skel[gp] = delta;
    } else {
        float s = g_skel[gp];
        g_skel[gp] = s + fmaxf(delta - s * delta, 0.0f);
    }
}

// ---------------------------------------------------------------------------
// Endpoints + per-slice reductions:
// nsum = 3x3 sum of skel + 9*center (zero padding); ep = exp(-(nsum-11)^2)*skel
// accumulate per-slice: sum(ep), sum(ep*y), sum(ep*x)
__global__ void __launch_bounds__(1024) endpoint_kernel() {
    __shared__ float s_sk[34][36];
    const int slice = blockIdx.z;
    const int gx0 = blockIdx.x * 32;
    const int gy0 = blockIdx.y * 32;
    const int t = threadIdx.y * 32 + threadIdx.x;
    const float* base = g_skel + slice * HW;

    for (int idx = t; idx < 34 * 34; idx += 1024) {
        int j = idx / 34, i = idx - j * 34;
        int gy = gy0 + j - 1, gx = gx0 + i - 1;
        float v = 0.0f;
        if ((unsigned)gy < IMG_H && (unsigned)gx < IMG_W)
            v = __ldg(base + gy * IMG_W + gx);
        s_sk[j][i] = v;
    }
    __syncthreads();

    const int ty = threadIdx.y, tx = threadIdx.x;
    float c = s_sk[ty + 1][tx + 1];
    float nsum = 9.0f * c;
    #pragma unroll
    for (int dj = 0; dj < 3; dj++)
        #pragma unroll
        for (int di = 0; di < 3; di++)
            nsum += s_sk[ty + dj][tx + di];
    float d = nsum - 11.0f;
    float ep = expf(-d * d) * c;

    double e  = (double)ep;
    double ey = (double)ep * (double)(gy0 + ty);
    double ex = (double)ep * (double)(gx0 + tx);

    __shared__ double red[32][3];
    unsigned lane = t & 31u, wid = t >> 5;
    #pragma unroll
    for (int o = 16; o > 0; o >>= 1) {
        e  += __shfl_down_sync(0xffffffffu, e, o);
        ey += __shfl_down_sync(0xffffffffu, ey, o);
        ex += __shfl_down_sync(0xffffffffu, ex, o);
    }
    if (lane == 0) { red[wid][0] = e; red[wid][1] = ey; red[wid][2] = ex; }
    __syncthreads();
    if (wid == 0) {
        e  = red[lane][0];
        ey = red[lane][1];
        ex = red[lane][2];
        #pragma unroll
        for (int o = 16; o > 0; o >>= 1) {
            e  += __shfl_down_sync(0xffffffffu, e, o);
            ey += __shfl_down_sync(0xffffffffu, ey, o);
            ex += __shfl_down_sync(0xffffffffu, ex, o);
        }
        if (lane == 0) {
            atomicAdd(&g_acc[slice * 3 + 0], e);
            atomicAdd(&g_acc[slice * 3 + 1], ey);
            atomicAdd(&g_acc[slice * 3 + 2], ex);
        }
    }
}

// ---------------------------------------------------------------------------
__global__ void final_kernel(float* out) {
    if (threadIdx.x == 0 && blockIdx.x == 0) {
        double dist = 0.0, cnt = 0.0;
        for (int b = 0; b < BATCH; b++) {
            double tp = g_acc[b * 3 + 0];
            double yp = g_acc[b * 3 + 1];
            double xp = g_acc[b * 3 + 2];
            double tt = g_acc[(BATCH + b) * 3 + 0];
            double yt = g_acc[(BATCH + b) * 3 + 1];
            double xt = g_acc[(BATCH + b) * 3 + 2];
            double ycp = yp / (tp + 1e-8), xcp = xp / (tp + 1e-8);
            double yct = yt / (tt + 1e-8), xct = xt / (tt + 1e-8);
            double dy = ycp - yct, dx = xcp - xct;
            dist += sqrt(dy * dy + dx * dx);
            cnt += fabs(tp - tt) / (tp + tt + 1e-8);
        }
        dist /= (double)BATCH;
        cnt  /= (double)BATCH;
        double diag = sqrt((double)IMG_H * IMG_H + (double)IMG_W * IMG_W);
        double distance_loss = dist / (diag * 1.0 /*TAU*/ + 1e-8);
        double ep_loss = distance_loss + 1.0 /*LAMBDA_COUNT*/ * cnt;
        double inter = g_acc[48], sp = g_acc[49], st = g_acc[50];
        double dice = 1.0 - (2.0 * inter + 1.0) / (st + sp + 1.0);
        out[0] = (float)(0.85 * dice + 0.15 * ep_loss);
    }
}

// ---------------------------------------------------------------------------
extern "C" void kernel_launch(void* const* d_in, const int* in_sizes, int n_in,
                              void* d_out, int out_size) {
    // Identify inputs by element count (net = 8*2*512*512, y_true = 8*1*512*512)
    const float* net;
    const int* ytrue;
    if (in_sizes[0] == BATCH * 2 * HW) {
        net = (const float*)d_in[0];
        ytrue = (const int*)d_in[1];
    } else {
        net = (const float*)d_in[1];
        ytrue = (const int*)d_in[0];
    }
    float* out = (float*)d_out;

    zero_acc_kernel<<<1, 64>>>();
    init_kernel<<<1024, 256>>>(net, ytrue);

    dim3 grid(IMG_W / 32, IMG_H / 32, NSLICE);
    dim3 blk(32, 32);

    // initial skel = relu(img - open(img)); img unchanged
    morph_kernel<false, true><<<grid, blk>>>(1);

    // 40 iterations, ping-pong img buffers
    int inA = 1;
    for (int k = 0; k < NUM_ITER; k++) {
        morph_kernel<true, false><<<grid, blk>>>(inA);
        inA ^= 1;
    }

    endpoint_kernel<<<grid, blk>>>();
    final_kernel<<<1, 1>>>(out);
}

// round 8
// speedup vs baseline: 2.2122x; 2.2122x over previous
#include <cuda_runtime.h>
#include <math_constants.h>
#include <math.h>

// Problem constants (shapes fixed by setup_inputs)
#define IMG_H 512
#define IMG_W 512
#define HW (IMG_H * IMG_W)
#define BATCH 8
#define NSLICE 16          // slices 0..7 = pred prob, 8..15 = y_true as float
#define NUM_ITER 40

#define FUSE 5             // skeleton iterations fused per kernel
#define RAD (FUSE + 2)     // halo radius = 7
#define S0 (32 + 2 * RAD)  // A0 tile extent = 46
#define SPITCH 48          // smem row pitch

// Scratch (static device globals — no allocation)
__device__ float  g_imgA[NSLICE * HW];
__device__ float  g_imgB[NSLICE * HW];
__device__ float  g_skel[NSLICE * HW];
// g_acc: [slice*3 + {sum_ep, sum_ep*y, sum_ep*x}] for slice 0..15,
//        [48]=dice inter, [49]=sum_pred, [50]=sum_true
__device__ double g_acc[64];

// ---------------------------------------------------------------------------
__global__ void zero_acc_kernel() {
    if (threadIdx.x < 64) g_acc[threadIdx.x] = 0.0;
}

// ---------------------------------------------------------------------------
// Init: pred prob = softmax fg = 1/(1+exp(x0-x1)); slices 8..15 = float(y_true).
// Also accumulates the dice sums (inter, sum_pred, sum_true).
__global__ void __launch_bounds__(256) init_kernel(const float* __restrict__ net,
                                                   const int* __restrict__ ytrue) {
    double inter = 0.0, sp = 0.0, st = 0.0;
    const int total = BATCH * HW;
    for (int idx = blockIdx.x * blockDim.x + threadIdx.x; idx < total;
         idx += gridDim.x * blockDim.x) {
        int b = idx / HW;
        int p = idx - b * HW;
        float x0 = net[(b * 2 + 0) * HW + p];
        float x1 = net[(b * 2 + 1) * HW + p];
        float pr = 1.0f / (1.0f + expf(x0 - x1));
        float tv = (float)ytrue[idx];
        g_imgA[idx] = pr;
        g_imgA[BATCH * HW + idx] = tv;
        inter += (double)(tv * pr);
        sp += (double)pr;
        st += (double)tv;
    }
    __shared__ double red[8][3];
    unsigned lane = threadIdx.x & 31u, wid = threadIdx.x >> 5;
    #pragma unroll
    for (int o = 16; o > 0; o >>= 1) {
        inter += __shfl_down_sync(0xffffffffu, inter, o);
        sp    += __shfl_down_sync(0xffffffffu, sp, o);
        st    += __shfl_down_sync(0xffffffffu, st, o);
    }
    if (lane == 0) { red[wid][0] = inter; red[wid][1] = sp; red[wid][2] = st; }
    __syncthreads();
    if (wid == 0) {
        inter = (lane < 8) ? red[lane][0] : 0.0;
        sp    = (lane < 8) ? red[lane][1] : 0.0;
        st    = (lane < 8) ? red[lane][2] : 0.0;
        #pragma unroll
        for (int o = 4; o > 0; o >>= 1) {
            inter += __shfl_down_sync(0xffffffffu, inter, o);
            sp    += __shfl_down_sync(0xffffffffu, sp, o);
            st    += __shfl_down_sync(0xffffffffu, st, o);
        }
        if (lane == 0) {
            atomicAdd(&g_acc[48], inter);
            atomicAdd(&g_acc[49], sp);
            atomicAdd(&g_acc[50], st);
        }
    }
}

// ---------------------------------------------------------------------------
// Fused morphology: FUSE soft_skel iterations in one kernel.
//   Chain: A_{k+1} = erode(A_k) computed for k=0..FUSE (ping-pong smem).
//   Iteration u's open = dilate(A_{u+1}); skel update uses center(A_u).
//   INIT additionally performs u=0: skel = relu(A0 - dilate(A1)).
//   New image written = center(A_FUSE).
// erode = min over 5-pt cross (+inf padding), dilate = 3x3 max (-inf padding).
template <bool INIT, bool BORDER>
__device__ __forceinline__ void morph_body(
    const float* __restrict__ img_in, float* __restrict__ img_out,
    float (*buf)[S0][SPITCH]) {

    const int slice = blockIdx.z;
    const int gx0 = blockIdx.x * 32;
    const int gy0 = blockIdx.y * 32;
    const int tx = threadIdx.x, ty = threadIdx.y;
    const float INF = CUDART_INF_F;
    const float* base = img_in + slice * HW;
    const int gp = slice * HW + (gy0 + ty) * IMG_W + (gx0 + tx);

    // Load skel early (hidden under halo load latency)
    float skel = INIT ? 0.0f : g_skel[gp];

    // ---- Load A0 halo: S0 x S0, OOB -> +inf ----
    #pragma unroll
    for (int yy = 0; yy < S0; yy += 32) {
        int y = yy + ty;
        if (y < S0) {
            #pragma unroll
            for (int xx = 0; xx < S0; xx += 32) {
                int x = xx + tx;
                if (x < S0) {
                    float v;
                    if (BORDER) {
                        int gy = gy0 + y - RAD, gx = gx0 + x - RAD;
                        v = ((unsigned)gy < IMG_H && (unsigned)gx < IMG_W)
                                ? base[gy * IMG_W + gx] : INF;
                    } else {
                        v = base[(gy0 + y - RAD) * IMG_W + (gx0 + x - RAD)];
                    }
                    buf[0][y][x] = v;
                }
            }
        }
    }
    __syncthreads();

    float c = INIT ? buf[0][RAD + ty][RAD + tx] : 0.0f;  // center(A0)
    float outv = 0.0f;
    int p = 0;

    #pragma unroll
    for (int k = 1; k <= FUSE + 1; ++k) {
        const int lo = k, hi = S0 - k;
        const int pn = p ^ 1;

        // ---- erode: A_k = min-cross(A_{k-1}) over region [lo, hi) ----
        #pragma unroll
        for (int yy = lo; yy < S0 - 1; yy += 32) {
            int y = yy + ty - (yy == lo ? (lo - lo) : 0); // plain: y = yy + ty
            y = yy + ty;
            if (y >= lo && y < hi) {
                #pragma unroll
                for (int xx = lo; xx < S0 - 1; xx += 32) {
                    int x = xx + tx;
                    if (x >= lo && x < hi) {
                        float v;
                        if (BORDER) {
                            int gy = gy0 + y - RAD, gx = gx0 + x - RAD;
                            if ((unsigned)gy < IMG_H && (unsigned)gx < IMG_W) {
                                float cc = buf[p][y][x];
                                float vv = fminf(buf[p][y - 1][x], buf[p][y + 1][x]);
                                float hh = fminf(buf[p][y][x - 1], buf[p][y][x + 1]);
                                v = fminf(cc, fminf(vv, hh));
                            } else {
                                v = INF;
                            }
                        } else {
                            float cc = buf[p][y][x];
                            float vv = fminf(buf[p][y - 1][x], buf[p][y + 1][x]);
                            float hh = fminf(buf[p][y][x - 1], buf[p][y][x + 1]);
                            v = fminf(cc, fminf(vv, hh));
                        }
                        buf[pn][y][x] = v;
                    }
                }
            }
        }
        __syncthreads();

        float c_next = buf[pn][RAD + ty][RAD + tx];  // center(A_k)
        if (k == FUSE) outv = c_next;

        // ---- skel update u = k-1 (INIT: u>=0; else u>=1) ----
        if (INIT || k >= 2) {
            float open = -INF;
            if (BORDER) {
                #pragma unroll
                for (int dj = -1; dj <= 1; dj++) {
                    #pragma unroll
                    for (int di = -1; di <= 1; di++) {
                        int gy = gy0 + ty + dj, gx = gx0 + tx + di;
                        float tv = ((unsigned)gy < IMG_H && (unsigned)gx < IMG_W)
                                       ? buf[pn][RAD + ty + dj][RAD + tx + di] : -INF;
                        open = fmaxf(open, tv);
                    }
                }
            } else {
                #pragma unroll
                for (int dj = -1; dj <= 1; dj++)
                    #pragma unroll
                    for (int di = -1; di <= 1; di++)
                        open = fmaxf(open, buf[pn][RAD + ty + dj][RAD + tx + di]);
            }
            float dlt = fmaxf(c - open, 0.0f);
            if (INIT && k == 1) {
                skel = dlt;
            } else {
                skel = skel + fmaxf(dlt - skel * dlt, 0.0f);
            }
        }
        c = c_next;
        p = pn;
    }

    img_out[gp] = outv;
    g_skel[gp] = skel;
}

template <bool INIT>
__global__ void __launch_bounds__(1024) morph_fused_kernel(int inA) {
    __shared__ float buf[2][S0][SPITCH];
    const float* img_in  = inA ? g_imgA : g_imgB;
    float*       img_out = inA ? g_imgB : g_imgA;
    const int gx0 = blockIdx.x * 32, gy0 = blockIdx.y * 32;
    bool border = (gx0 < RAD) || (gy0 < RAD) ||
                  (gx0 + 32 + RAD > IMG_W) || (gy0 + 32 + RAD > IMG_H);
    if (border)
        morph_body<INIT, true>(img_in, img_out, buf);
    else
        morph_body<INIT, false>(img_in, img_out, buf);
}

// ---------------------------------------------------------------------------
// Endpoints + per-slice reductions:
// nsum = 3x3 sum of skel + 9*center (zero padding); ep = exp(-(nsum-11)^2)*skel
__global__ void __launch_bounds__(1024) endpoint_kernel() {
    __shared__ float s_sk[34][36];
    const int slice = blockIdx.z;
    const int gx0 = blockIdx.x * 32;
    const int gy0 = blockIdx.y * 32;
    const int t = threadIdx.y * 32 + threadIdx.x;
    const float* base = g_skel + slice * HW;

    for (int idx = t; idx < 34 * 34; idx += 1024) {
        int j = idx / 34, i = idx - j * 34;
        int gy = gy0 + j - 1, gx = gx0 + i - 1;
        float v = 0.0f;
        if ((unsigned)gy < IMG_H && (unsigned)gx < IMG_W)
            v = __ldg(base + gy * IMG_W + gx);
        s_sk[j][i] = v;
    }
    __syncthreads();

    const int ty = threadIdx.y, tx = threadIdx.x;
    float c = s_sk[ty + 1][tx + 1];
    float nsum = 9.0f * c;
    #pragma unroll
    for (int dj = 0; dj < 3; dj++)
        #pragma unroll
        for (int di = 0; di < 3; di++)
            nsum += s_sk[ty + dj][tx + di];
    float d = nsum - 11.0f;
    float ep = expf(-d * d) * c;

    double e  = (double)ep;
    double ey = (double)ep * (double)(gy0 + ty);
    double ex = (double)ep * (double)(gx0 + tx);

    __shared__ double red[32][3];
    unsigned lane = t & 31u, wid = t >> 5;
    #pragma unroll
    for (int o = 16; o > 0; o >>= 1) {
        e  += __shfl_down_sync(0xffffffffu, e, o);
        ey += __shfl_down_sync(0xffffffffu, ey, o);
        ex += __shfl_down_sync(0xffffffffu, ex, o);
    }
    if (lane == 0) { red[wid][0] = e; red[wid][1] = ey; red[wid][2] = ex; }
    __syncthreads();
    if (wid == 0) {
        e  = red[lane][0];
        ey = red[lane][1];
        ex = red[lane][2];
        #pragma unroll
        for (int o = 16; o > 0; o >>= 1) {
            e  += __shfl_down_sync(0xffffffffu, e, o);
            ey += __shfl_down_sync(0xffffffffu, ey, o);
            ex += __shfl_down_sync(0xffffffffu, ex, o);
        }
        if (lane == 0) {
            atomicAdd(&g_acc[slice * 3 + 0], e);
            atomicAdd(&g_acc[slice * 3 + 1], ey);
            atomicAdd(&g_acc[slice * 3 + 2], ex);
        }
    }
}

// ---------------------------------------------------------------------------
__global__ void final_kernel(float* out) {
    if (threadIdx.x == 0 && blockIdx.x == 0) {
        double dist = 0.0, cnt = 0.0;
        for (int b = 0; b < BATCH; b++) {
            double tp = g_acc[b * 3 + 0];
            double yp = g_acc[b * 3 + 1];
            double xp = g_acc[b * 3 + 2];
            double tt = g_acc[(BATCH + b) * 3 + 0];
            double yt = g_acc[(BATCH + b) * 3 + 1];
            double xt = g_acc[(BATCH + b) * 3 + 2];
            double ycp = yp / (tp + 1e-8), xcp = xp / (tp + 1e-8);
            double yct = yt / (tt + 1e-8), xct = xt / (tt + 1e-8);
            double dy = ycp - yct, dx = xcp - xct;
            dist += sqrt(dy * dy + dx * dx);
            cnt += fabs(tp - tt) / (tp + tt + 1e-8);
        }
        dist /= (double)BATCH;
        cnt  /= (double)BATCH;
        double diag = sqrt((double)IMG_H * IMG_H + (double)IMG_W * IMG_W);
        double distance_loss = dist / (diag * 1.0 /*TAU*/ + 1e-8);
        double ep_loss = distance_loss + 1.0 /*LAMBDA_COUNT*/ * cnt;
        double inter = g_acc[48], sp = g_acc[49], st = g_acc[50];
        double dice = 1.0 - (2.0 * inter + 1.0) / (st + sp + 1.0);
        out[0] = (float)(0.85 * dice + 0.15 * ep_loss);
    }
}

// ---------------------------------------------------------------------------
extern "C" void kernel_launch(void* const* d_in, const int* in_sizes, int n_in,
                              void* d_out, int out_size) {
    const float* net;
    const int* ytrue;
    if (in_sizes[0] == BATCH * 2 * HW) {
        net = (const float*)d_in[0];
        ytrue = (const int*)d_in[1];
    } else {
        net = (const float*)d_in[1];
        ytrue = (const int*)d_in[0];
    }
    float* out = (float*)d_out;

    zero_acc_kernel<<<1, 64>>>();
    init_kernel<<<1024, 256>>>(net, ytrue);

    dim3 grid(IMG_W / 32, IMG_H / 32, NSLICE);
    dim3 blk(32, 32);

    // First fused kernel: initial skel + FUSE iterations (reads A, writes B)
    morph_fused_kernel<true><<<grid, blk>>>(1);

    // Remaining (NUM_ITER - FUSE) iterations in chunks of FUSE, ping-ponging
    int inA = 0;
    for (int k = FUSE; k < NUM_ITER; k += FUSE) {
        morph_fused_kernel<false><<<grid, blk>>>(inA);
        inA ^= 1;
    }

    endpoint_kernel<<<grid, blk>>>();
    final_kernel<<<1, 1>>>(out);
}

// round 9
// speedup vs baseline: 2.2288x; 1.0075x over previous
#include <cuda_runtime.h>
#include <math_constants.h>
#include <math.h>

// Problem constants (shapes fixed by setup_inputs)
#define IMG_H 512
#define IMG_W 512
#define HW (IMG_H * IMG_W)
#define BATCH 8
#define NSLICE 16          // slices 0..7 = pred prob, 8..15 = y_true as float
#define NUM_ITER 40

#define FUSE 5             // skeleton iterations fused per kernel
#define OUTC 18            // valid output columns per warp (32 - 2*(FUSE+2))
#define NCG 29             // ceil(512/18) column groups
#define NRG 8              // row groups of 64 rows
#define ROWS_PER_WARP 64

// Scratch (static device globals — no allocation)
__device__ float  g_imgA[NSLICE * HW];
__device__ float  g_imgB[NSLICE * HW];
__device__ float  g_skel[NSLICE * HW];
// g_acc: [slice*3 + {sum_ep, sum_ep*y, sum_ep*x}] for slice 0..15,
//        [48]=dice inter, [49]=sum_pred, [50]=sum_true
__device__ double g_acc[64];

// ---------------------------------------------------------------------------
__global__ void zero_acc_kernel() {
    if (threadIdx.x < 64) g_acc[threadIdx.x] = 0.0;
}

// ---------------------------------------------------------------------------
// Init (float4): pred prob = 1/(1+exp(x0-x1)); slices 8..15 = float(y_true).
// Accumulates dice sums. Grid: (HW/1024, BATCH), block 256, 4 px/thread.
__global__ void __launch_bounds__(256) init_kernel(const float4* __restrict__ net,
                                                   const int4* __restrict__ ytrue) {
    const int b = blockIdx.y;
    const int p = blockIdx.x * 256 + threadIdx.x;          // float4 index
    const int Q = HW / 4;

    float4 x0 = net[(b * 2 + 0) * Q + p];
    float4 x1 = net[(b * 2 + 1) * Q + p];
    int4  yv = ytrue[b * Q + p];

    float4 pr;
    pr.x = 1.0f / (1.0f + expf(x0.x - x1.x));
    pr.y = 1.0f / (1.0f + expf(x0.y - x1.y));
    pr.z = 1.0f / (1.0f + expf(x0.z - x1.z));
    pr.w = 1.0f / (1.0f + expf(x0.w - x1.w));
    float4 tv = make_float4((float)yv.x, (float)yv.y, (float)yv.z, (float)yv.w);

    ((float4*)g_imgA)[b * Q + p] = pr;
    ((float4*)g_imgA)[(BATCH + b) * Q + p] = tv;

    double inter = (double)(tv.x * pr.x + tv.y * pr.y + tv.z * pr.z + tv.w * pr.w);
    double sp = (double)(pr.x + pr.y + pr.z + pr.w);
    double st = (double)(tv.x + tv.y + tv.z + tv.w);

    __shared__ double red[8][3];
    unsigned lane = threadIdx.x & 31u, wid = threadIdx.x >> 5;
    #pragma unroll
    for (int o = 16; o > 0; o >>= 1) {
        inter += __shfl_down_sync(0xffffffffu, inter, o);
        sp    += __shfl_down_sync(0xffffffffu, sp, o);
        st    += __shfl_down_sync(0xffffffffu, st, o);
    }
    if (lane == 0) { red[wid][0] = inter; red[wid][1] = sp; red[wid][2] = st; }
    __syncthreads();
    if (wid == 0) {
        inter = (lane < 8) ? red[lane][0] : 0.0;
        sp    = (lane < 8) ? red[lane][1] : 0.0;
        st    = (lane < 8) ? red[lane][2] : 0.0;
        #pragma unroll
        for (int o = 4; o > 0; o >>= 1) {
            inter += __shfl_down_sync(0xffffffffu, inter, o);
            sp    += __shfl_down_sync(0xffffffffu, sp, o);
            st    += __shfl_down_sync(0xffffffffu, st, o);
        }
        if (lane == 0) {
            atomicAdd(&g_acc[48], inter);
            atomicAdd(&g_acc[49], sp);
            atomicAdd(&g_acc[50], st);
        }
    }
}

// ---------------------------------------------------------------------------
// Warp-register pipelined morphology. One warp owns 32 columns (18 valid
// outputs) and sweeps 64 output rows (+14 halo). All stencils via register
// row-windows (vertical) + warp shuffles (horizontal). No shared memory.
//
// erode = min over 5-pt cross (+inf outside image)
// dilate = 3x3 max (-inf outside image)
// Iteration u (local): delta = relu(A_u - dilate(A_{u+1})), A_k = erode^k(A_0)
//   -> stage k=u+1 pairs center(A_{k-1}) with dilate(A_k).
// INIT also does k=1 (sets skel); non-INIT does k=2..6 on loaded skel.

__device__ __forceinline__ float erode5(float m2, float m1, float n, bool valid) {
    float up = __shfl_up_sync(0xffffffffu, m1, 1);
    float dn = __shfl_down_sync(0xffffffffu, m1, 1);
    float e = fminf(fminf(m1, fminf(m2, n)), fminf(up, dn));
    return valid ? e : CUDART_INF_F;
}

__device__ __forceinline__ float hmax3(float v, bool valid) {
    float m = valid ? v : -CUDART_INF_F;
    float up = __shfl_up_sync(0xffffffffu, m, 1);
    float dn = __shfl_down_sync(0xffffffffu, m, 1);
    return fmaxf(fmaxf(m, up), dn);
}

template <bool INIT>
__global__ void __launch_bounds__(256) morph_warp_kernel(int inA) {
    const float* __restrict__ img_in  = inA ? g_imgA : g_imgB;
    float* __restrict__       img_out = inA ? g_imgB : g_imgA;

    const int lane = threadIdx.x & 31;
    const int w = blockIdx.x * 8 + (threadIdx.x >> 5);   // 3712 warps total
    const int slice = w / (NCG * NRG);
    int rem = w - slice * (NCG * NRG);
    const int rg = rem / NCG;
    const int cg = rem - rg * NCG;
    const int col = cg * OUTC + lane - 7;
    const bool colv = (unsigned)col < (unsigned)IMG_W;
    const int r0 = rg * ROWS_PER_WARP;
    const float* __restrict__ base = img_in + slice * HW;
    float* __restrict__ outp = img_out + slice * HW;
    float* __restrict__ skp  = g_skel + slice * HW;
    const bool owner = (lane >= 7) && (lane < 25) && colv;

    const float INF = CUDART_INF_F;
    float a0n=INF,a0m1=INF,a0m2=INF;
    float a1n=INF,a1m1=INF,a1m2=INF;
    float a2n=INF,a2m1=INF,a2m2=INF;
    float a3n=INF,a3m1=INF,a3m2=INF;
    float a4n=INF,a4m1=INF,a4m2=INF;
    float a5n=INF,a5m1=INF,a5m2=INF;
    float a6n=INF;
    float h1n=-INF,h1m1=-INF,h1m2=-INF;   // INIT only (dead otherwise)
    float h2n=-INF,h2m1=-INF,h2m2=-INF;
    float h3n=-INF,h3m1=-INF,h3m2=-INF;
    float h4n=-INF,h4m1=-INF,h4m2=-INF;
    float h5n=-INF,h5m1=-INF,h5m2=-INF;
    float h6n=-INF,h6m1=-INF,h6m2=-INF;
    float dl0=0.f,dl1=0.f,dl2=0.f,dl3=0.f,dl4=0.f,dl5=0.f;

    #pragma unroll 2
    for (int t = r0 - 7; t <= r0 + 70; ++t) {
        // load input row t (OOB -> +inf, the erode-neutral pad)
        float ld = INF;
        if (colv && (unsigned)t < (unsigned)IMG_H)
            ld = __ldg(base + t * IMG_W + col);

        // skel delay line: dl0 = row t-2 ... dl5 = row t-7 (after shift)
        dl5 = dl4; dl4 = dl3; dl3 = dl2; dl2 = dl1; dl1 = dl0;
        if (INIT) {
            dl0 = 0.0f;
        } else {
            int rs = t - 2;
            dl0 = (owner && rs >= r0 && rs < r0 + ROWS_PER_WARP)
                      ? skp[rs * IMG_W + col] : 0.0f;
        }

        // erode chain: a_k row t-k
        a0m2 = a0m1; a0m1 = a0n; a0n = ld;
        float e;
        e = erode5(a0m2, a0m1, a0n, colv && (unsigned)(t-1) < (unsigned)IMG_H);
        a1m2 = a1m1; a1m1 = a1n; a1n = e;
        e = erode5(a1m2, a1m1, a1n, colv && (unsigned)(t-2) < (unsigned)IMG_H);
        a2m2 = a2m1; a2m1 = a2n; a2n = e;
        e = erode5(a2m2, a2m1, a2n, colv && (unsigned)(t-3) < (unsigned)IMG_H);
        a3m2 = a3m1; a3m1 = a3n; a3n = e;
        e = erode5(a3m2, a3m1, a3n, colv && (unsigned)(t-4) < (unsigned)IMG_H);
        a4m2 = a4m1; a4m1 = a4n; a4n = e;
        e = erode5(a4m2, a4m1, a4n, colv && (unsigned)(t-5) < (unsigned)IMG_H);
        a5m2 = a5m1; a5m1 = a5n; a5n = e;
        e = erode5(a5m2, a5m1, a5n, colv && (unsigned)(t-6) < (unsigned)IMG_H);
        a6n = e;

        // dilate + skel update per fused iteration
        // stage k: h_k = hmax3(a_k row t-k); dil row t-k-1; c = a_{k-1} row t-k-1
        #define DO_K(K, APREV_M2, ACUR_N, HN, HM1, HM2, DL, SETFIRST)           \
        {                                                                        \
            HM2 = HM1; HM1 = HN;                                                 \
            HN = hmax3(ACUR_N, colv && (unsigned)(t-(K)) < (unsigned)IMG_H);     \
            float dil = fmaxf(fmaxf(HM2, HM1), HN);                              \
            float dlt = fmaxf(APREV_M2 - dil, 0.0f);                             \
            if (SETFIRST) DL = dlt;                                              \
            else          DL = DL + fmaxf(dlt - DL * dlt, 0.0f);                 \
        }

        if (INIT) DO_K(1, a0m2, a1n, h1n, h1m1, h1m2, dl0, true);
        DO_K(2, a1m2, a2n, h2n, h2m1, h2m2, dl1, false);
        DO_K(3, a2m2, a3n, h3n, h3m1, h3m2, dl2, false);
        DO_K(4, a3m2, a4n, h4n, h4m1, h4m2, dl3, false);
        DO_K(5, a4m2, a5n, h5n, h5m1, h5m2, dl4, false);
        DO_K(6, a5m2, a6n, h6n, h6m1, h6m2, dl5, false);
        #undef DO_K

        // stores
        if (owner) {
            int ro = t - 5;                       // a5 = new image row
            if (ro >= r0 && ro < r0 + ROWS_PER_WARP)
                outp[ro * IMG_W + col] = a5n;
            int rs = t - 7;                       // skel row fully updated
            if (rs >= r0 && rs < r0 + ROWS_PER_WARP)
                skp[rs * IMG_W + col] = dl5;
        }
    }
}

// ---------------------------------------------------------------------------
// Endpoints + per-slice reductions:
// nsum = 3x3 sum of skel + 9*center (zero padding); ep = exp(-(nsum-11)^2)*skel
__global__ void __launch_bounds__(1024) endpoint_kernel() {
    __shared__ float s_sk[34][36];
    const int slice = blockIdx.z;
    const int gx0 = blockIdx.x * 32;
    const int gy0 = blockIdx.y * 32;
    const int t = threadIdx.y * 32 + threadIdx.x;
    const float* base = g_skel + slice * HW;

    for (int idx = t; idx < 34 * 34; idx += 1024) {
        int j = idx / 34, i = idx - j * 34;
        int gy = gy0 + j - 1, gx = gx0 + i - 1;
        float v = 0.0f;
        if ((unsigned)gy < IMG_H && (unsigned)gx < IMG_W)
            v = __ldg(base + gy * IMG_W + gx);
        s_sk[j][i] = v;
    }
    __syncthreads();

    const int ty = threadIdx.y, tx = threadIdx.x;
    float c = s_sk[ty + 1][tx + 1];
    float nsum = 9.0f * c;
    #pragma unroll
    for (int dj = 0; dj < 3; dj++)
        #pragma unroll
        for (int di = 0; di < 3; di++)
            nsum += s_sk[ty + dj][tx + di];
    float d = nsum - 11.0f;
    float ep = expf(-d * d) * c;

    double e  = (double)ep;
    double ey = (double)ep * (double)(gy0 + ty);
    double ex = (double)ep * (double)(gx0 + tx);

    __shared__ double red[32][3];
    unsigned lane = t & 31u, wid = t >> 5;
    #pragma unroll
    for (int o = 16; o > 0; o >>= 1) {
        e  += __shfl_down_sync(0xffffffffu, e, o);
        ey += __shfl_down_sync(0xffffffffu, ey, o);
        ex += __shfl_down_sync(0xffffffffu, ex, o);
    }
    if (lane == 0) { red[wid][0] = e; red[wid][1] = ey; red[wid][2] = ex; }
    __syncthreads();
    if (wid == 0) {
        e  = red[lane][0];
        ey = red[lane][1];
        ex = red[lane][2];
        #pragma unroll
        for (int o = 16; o > 0; o >>= 1) {
            e  += __shfl_down_sync(0xffffffffu, e, o);
            ey += __shfl_down_sync(0xffffffffu, ey, o);
            ex += __shfl_down_sync(0xffffffffu, ex, o);
        }
        if (lane == 0) {
            atomicAdd(&g_acc[slice * 3 + 0], e);
            atomicAdd(&g_acc[slice * 3 + 1], ey);
            atomicAdd(&g_acc[slice * 3 + 2], ex);
        }
    }
}

// ---------------------------------------------------------------------------
__global__ void final_kernel(float* out) {
    if (threadIdx.x == 0 && blockIdx.x == 0) {
        double dist = 0.0, cnt = 0.0;
        for (int b = 0; b < BATCH; b++) {
            double tp = g_acc[b * 3 + 0];
            double yp = g_acc[b * 3 + 1];
            double xp = g_acc[b * 3 + 2];
            double tt = g_acc[(BATCH + b) * 3 + 0];
            double yt = g_acc[(BATCH + b) * 3 + 1];
            double xt = g_acc[(BATCH + b) * 3 + 2];
            double ycp = yp / (tp + 1e-8), xcp = xp / (tp + 1e-8);
            double yct = yt / (tt + 1e-8), xct = xt / (tt + 1e-8);
            double dy = ycp - yct, dx = xcp - xct;
            dist += sqrt(dy * dy + dx * dx);
            cnt += fabs(tp - tt) / (tp + tt + 1e-8);
        }
        dist /= (double)BATCH;
        cnt  /= (double)BATCH;
        double diag = sqrt((double)IMG_H * IMG_H + (double)IMG_W * IMG_W);
        double distance_loss = dist / (diag * 1.0 /*TAU*/ + 1e-8);
        double ep_loss = distance_loss + 1.0 /*LAMBDA_COUNT*/ * cnt;
        double inter = g_acc[48], sp = g_acc[49], st = g_acc[50];
        double dice = 1.0 - (2.0 * inter + 1.0) / (st + sp + 1.0);
        out[0] = (float)(0.85 * dice + 0.15 * ep_loss);
    }
}

// ---------------------------------------------------------------------------
extern "C" void kernel_launch(void* const* d_in, const int* in_sizes, int n_in,
                              void* d_out, int out_size) {
    const float* net;
    const int* ytrue;
    if (in_sizes[0] == BATCH * 2 * HW) {
        net = (const float*)d_in[0];
        ytrue = (const int*)d_in[1];
    } else {
        net = (const float*)d_in[1];
        ytrue = (const int*)d_in[0];
    }
    float* out = (float*)d_out;

    zero_acc_kernel<<<1, 64>>>();
    init_kernel<<<dim3(HW / 1024, BATCH), 256>>>((const float4*)net,
                                                 (const int4*)ytrue);

    // 3712 warps = 464 blocks of 8 warps
    const int MBLOCKS = (NCG * NRG * NSLICE) / 8;

    // First fused kernel: initial skel + FUSE iterations (reads A, writes B)
    morph_warp_kernel<true><<<MBLOCKS, 256>>>(1);

    // Remaining (NUM_ITER - FUSE) iterations in chunks of FUSE, ping-ponging
    int inA = 0;
    for (int k = FUSE; k < NUM_ITER; k += FUSE) {
        morph_warp_kernel<false><<<MBLOCKS, 256>>>(inA);
        inA ^= 1;
    }

    dim3 grid(IMG_W / 32, IMG_H / 32, NSLICE);
    dim3 blk(32, 32);
    endpoint_kernel<<<grid, blk>>>();
    final_kernel<<<1, 1>>>(out);
}

// round 14
// speedup vs baseline: 2.7554x; 1.2363x over previous
#include <cuda_runtime.h>
#include <math_constants.h>
#include <math.h>

// Problem constants (shapes fixed by setup_inputs)
#define IMG_H 512
#define IMG_W 512
#define HW (IMG_H * IMG_W)
#define BATCH 8
#define NSLICE 16          // slices 0..7 = pred prob, 8..15 = y_true as float
#define NUM_ITER 40

#define FUSE 5             // skeleton iterations fused per kernel
#define RAD 8              // halo radius (need >= FUSE+2 = 7; 8 keeps float2 alignment)
#define TILE 64
#define SR 80              // smem extent rows/cols = TILE + 2*RAD
#define SP2 40             // float2 pairs per row
#define SPF 80             // floats per row
#define SMEM_BYTES (2 * SR * SP2 * (int)sizeof(float2))   // 51200

// Scratch (static device globals — no allocation)
__device__ float  g_imgA[NSLICE * HW];
__device__ float  g_imgB[NSLICE * HW];
__device__ float  g_skel[NSLICE * HW];
// g_acc: [slice*3 + {sum_ep, sum_ep*y, sum_ep*x}] for slice 0..15,
//        [48]=dice inter, [49]=sum_pred, [50]=sum_true
__device__ double g_acc[64];

// ---------------------------------------------------------------------------
__global__ void zero_acc_kernel() {
    if (threadIdx.x < 64) g_acc[threadIdx.x] = 0.0;
}

// ---------------------------------------------------------------------------
// Init (float4): pred prob = 1/(1+exp(x0-x1)); slices 8..15 = float(y_true).
__global__ void __launch_bounds__(256) init_kernel(const float4* __restrict__ net,
                                                   const int4* __restrict__ ytrue) {
    const int b = blockIdx.y;
    const int p = blockIdx.x * 256 + threadIdx.x;          // float4 index
    const int Q = HW / 4;

    float4 x0 = net[(b * 2 + 0) * Q + p];
    float4 x1 = net[(b * 2 + 1) * Q + p];
    int4  yv = ytrue[b * Q + p];

    float4 pr;
    pr.x = 1.0f / (1.0f + expf(x0.x - x1.x));
    pr.y = 1.0f / (1.0f + expf(x0.y - x1.y));
    pr.z = 1.0f / (1.0f + expf(x0.z - x1.z));
    pr.w = 1.0f / (1.0f + expf(x0.w - x1.w));
    float4 tv = make_float4((float)yv.x, (float)yv.y, (float)yv.z, (float)yv.w);

    ((float4*)g_imgA)[b * Q + p] = pr;
    ((float4*)g_imgA)[(BATCH + b) * Q + p] = tv;

    double inter = (double)(tv.x * pr.x + tv.y * pr.y + tv.z * pr.z + tv.w * pr.w);
    double sp = (double)(pr.x + pr.y + pr.z + pr.w);
    double st = (double)(tv.x + tv.y + tv.z + tv.w);

    __shared__ double red[8][3];
    unsigned lane = threadIdx.x & 31u, wid = threadIdx.x >> 5;
    #pragma unroll
    for (int o = 16; o > 0; o >>= 1) {
        inter += __shfl_down_sync(0xffffffffu, inter, o);
        sp    += __shfl_down_sync(0xffffffffu, sp, o);
        st    += __shfl_down_sync(0xffffffffu, st, o);
    }
    if (lane == 0) { red[wid][0] = inter; red[wid][1] = sp; red[wid][2] = st; }
    __syncthreads();
    if (wid == 0) {
        inter = (lane < 8) ? red[lane][0] : 0.0;
        sp    = (lane < 8) ? red[lane][1] : 0.0;
        st    = (lane < 8) ? red[lane][2] : 0.0;
        #pragma unroll
        for (int o = 4; o > 0; o >>= 1) {
            inter += __shfl_down_sync(0xffffffffu, inter, o);
            sp    += __shfl_down_sync(0xffffffffu, sp, o);
            st    += __shfl_down_sync(0xffffffffu, st, o);
        }
        if (lane == 0) {
            atomicAdd(&g_acc[48], inter);
            atomicAdd(&g_acc[49], sp);
            atomicAdd(&g_acc[50], st);
        }
    }
}

// ---------------------------------------------------------------------------
// Fused morphology, 2x2 register-blocked. Tile 64x64, block 1024 threads
// (32x32, each thread owns a 2x2 quad). Dynamic smem: two 80x80 buffers
// (float2 pitch 40), ping-ponged across 6 erode stages.
//
// erode = min over 5-pt cross (+inf outside image)
// dilate = 3x3 max (-inf outside image)
// Iteration u: delta = relu(center(A_u) - dilate(A_{u+1})); A_k = erode^k(A0).
// Stage k valid region = [k, 80-k); positions outside hold garbage but are
// provably never read by any valid position (region shrinks 1/stage, stencil
// reach 1). Border blocks force +inf on erode stores / -inf on dilate taps
// at image-OOB positions (exact reference padding semantics).

template <bool INIT, bool BORDER>
__device__ __forceinline__ void morph2_body(
    const float* __restrict__ base, float* __restrict__ outp,
    float* __restrict__ skp, float2* bufA, float2* bufB) {

    const int tid = threadIdx.x;
    const int tx = tid & 31, ty = tid >> 5;
    const int gx0 = blockIdx.x * TILE;
    const int gy0 = blockIdx.y * TILE;
    const float INF = CUDART_INF_F;

    // ---- Load A0: 80x80 floats = 3200 float2 ----
    for (int q = tid; q < SR * SP2; q += 1024) {
        int y = q / SP2, p = q - y * SP2;
        int gy = gy0 + y - RAD, gx = gx0 + 2 * p - RAD;
        float2 v;
        if (BORDER) {
            bool iy = (unsigned)gy < (unsigned)IMG_H;
            v.x = (iy && (unsigned)gx < (unsigned)IMG_W) ? base[gy * IMG_W + gx] : INF;
            v.y = (iy && (unsigned)(gx + 1) < (unsigned)IMG_W) ? base[gy * IMG_W + gx + 1] : INF;
        } else {
            v = *(const float2*)(base + gy * IMG_W + gx);
        }
        bufA[y * SP2 + p] = v;
    }
    __syncthreads();

    // thread's output quad: rows oy0,oy1, pair po
    const int oy0 = RAD + 2 * ty, oy1 = oy0 + 1;
    const int po = RAD / 2 + tx;                       // cols RAD+2tx, RAD+2tx+1
    const int goy = gy0 + 2 * ty;                      // image row of quad top
    const int gox = gx0 + 2 * tx;                      // image col of quad left

    // cprev = centers of A0
    float c00, c01, c10, c11;
    {
        float2 a = bufA[oy0 * SP2 + po], b = bufA[oy1 * SP2 + po];
        c00 = a.x; c01 = a.y; c10 = b.x; c11 = b.y;
    }
    float s00, s01, s10, s11;
    if (INIT) {
        s00 = s01 = s10 = s11 = 0.0f;
    } else {
        float2 a = *(const float2*)(skp + goy * IMG_W + gox);
        float2 b = *(const float2*)(skp + (goy + 1) * IMG_W + gox);
        s00 = a.x; s01 = a.y; s10 = b.x; s11 = b.y;
    }
    float o00 = 0.f, o01 = 0.f, o10 = 0.f, o11 = 0.f;

    float2* P = bufA;
    float2* N = bufB;

    #pragma unroll
    for (int k = 1; k <= FUSE + 1; ++k) {
        // ---- erode stage k over full extent (1600 quads) ----
        const float* Pf = (const float*)P;
        #pragma unroll
        for (int qq = 0; qq < 2; ++qq) {
            int q = tid + qq * 1024;
            if (q < 1600) {
                int j = q / SP2, p = q - j * SP2;
                int y0 = 2 * j, y1 = y0 + 1;
                int yu = (j == 0) ? 0 : y0 - 1;
                int yd = (j == SP2 - 1) ? SR - 1 : y1 + 1;
                int cl = (p == 0) ? 0 : 2 * p - 1;
                int cr = (p == SP2 - 1) ? SPF - 1 : 2 * p + 2;
                float2 cu = P[yu * SP2 + p], c0 = P[y0 * SP2 + p];
                float2 c1 = P[y1 * SP2 + p], cd = P[yd * SP2 + p];
                float l0 = Pf[y0 * SPF + cl], l1 = Pf[y1 * SPF + cl];
                float r0 = Pf[y0 * SPF + cr], r1 = Pf[y1 * SPF + cr];
                float2 e0, e1;
                e0.x = fminf(fminf(c0.x, c0.y), fminf(fminf(cu.x, c1.x), l0));
                e0.y = fminf(fminf(c0.y, c0.x), fminf(fminf(cu.y, c1.y), r0));
                e1.x = fminf(fminf(c1.x, c1.y), fminf(fminf(c0.x, cd.x), l1));
                e1.y = fminf(fminf(c1.y, c1.x), fminf(fminf(c0.y, cd.y), r1));
                if (BORDER) {
                    int gyA = gy0 + y0 - RAD, gyB = gyA + 1;
                    int gxA = gx0 + 2 * p - RAD, gxB = gxA + 1;
                    bool ia = (unsigned)gyA < (unsigned)IMG_H;
                    bool ib = (unsigned)gyB < (unsigned)IMG_H;
                    bool ja = (unsigned)gxA < (unsigned)IMG_W;
                    bool jb = (unsigned)gxB < (unsigned)IMG_W;
                    e0.x = (ia && ja) ? e0.x : INF;
                    e0.y = (ia && jb) ? e0.y : INF;
                    e1.x = (ib && ja) ? e1.x : INF;
                    e1.y = (ib && jb) ? e1.y : INF;
                }
                N[y0 * SP2 + p] = e0;
                N[y1 * SP2 + p] = e1;
            }
        }
        __syncthreads();

        // ---- capture centers of A_k; dilate + skel update (iteration k-1) ----
        const float* Nf = (const float*)N;
        float n00, n01, n10, n11;
        {
            float2 t1 = N[oy0 * SP2 + po], t2 = N[oy1 * SP2 + po];
            n00 = t1.x; n01 = t1.y; n10 = t2.x; n11 = t2.y;
        }
        if (k == FUSE) { o00 = n00; o01 = n01; o10 = n10; o11 = n11; }

        if (INIT || k >= 2) {
            float rmx[4], rmy[4];
            #pragma unroll
            for (int r = 0; r < 4; ++r) {
                int yy = oy0 - 1 + r;
                float2 cc = N[yy * SP2 + po];
                float lf = Nf[yy * SPF + (RAD + 2 * tx - 1)];
                float rt = Nf[yy * SPF + (RAD + 2 * tx + 2)];
                if (BORDER) {
                    int gy = gy0 + yy - RAD;
                    bool iy = (unsigned)gy < (unsigned)IMG_H;
                    float cx = (iy && (unsigned)(gox)     < (unsigned)IMG_W) ? cc.x : -INF;
                    float cy = (iy && (unsigned)(gox + 1) < (unsigned)IMG_W) ? cc.y : -INF;
                    lf = (iy && (unsigned)(gox - 1) < (unsigned)IMG_W) ? lf : -INF;
                    rt = (iy && (unsigned)(gox + 2) < (unsigned)IMG_W) ? rt : -INF;
                    float m = fmaxf(cx, cy);
                    rmx[r] = fmaxf(m, lf);
                    rmy[r] = fmaxf(m, rt);
                } else {
                    float m = fmaxf(cc.x, cc.y);
                    rmx[r] = fmaxf(m, lf);
                    rmy[r] = fmaxf(m, rt);
                }
            }
            float op00 = fmaxf(fmaxf(rmx[0], rmx[1]), rmx[2]);
            float op01 = fmaxf(fmaxf(rmy[0], rmy[1]), rmy[2]);
            float op10 = fmaxf(fmaxf(rmx[1], rmx[2]), rmx[3]);
            float op11 = fmaxf(fmaxf(rmy[1], rmy[2]), rmy[3]);
            float d00 = fmaxf(c00 - op00, 0.0f);
            float d01 = fmaxf(c01 - op01, 0.0f);
            float d10 = fmaxf(c10 - op10, 0.0f);
            float d11 = fmaxf(c11 - op11, 0.0f);
            if (INIT && k == 1) {
                s00 = d00; s01 = d01; s10 = d10; s11 = d11;
            } else {
                s00 += fmaxf(d00 - s00 * d00, 0.0f);
                s01 += fmaxf(d01 - s01 * d01, 0.0f);
                s10 += fmaxf(d10 - s10 * d10, 0.0f);
                s11 += fmaxf(d11 - s11 * d11, 0.0f);
            }
        }
        c00 = n00; c01 = n01; c10 = n10; c11 = n11;
        float2* t = P; P = N; N = t;
        // No extra sync needed: next erode reads new P (just synced) and
        // writes old P, which no thread reads after the sync above.
    }

    // ---- store new image (A_FUSE centers) and skel ----
    *(float2*)(outp + goy * IMG_W + gox)       = make_float2(o00, o01);
    *(float2*)(outp + (goy + 1) * IMG_W + gox) = make_float2(o10, o11);
    *(float2*)(skp + goy * IMG_W + gox)        = make_float2(s00, s01);
    *(float2*)(skp + (goy + 1) * IMG_W + gox)  = make_float2(s10, s11);
}

template <bool INIT>
__global__ void __launch_bounds__(1024) morph2_kernel(int inA) {
    extern __shared__ float2 sdyn[];
    float2* bufA = sdyn;
    float2* bufB = sdyn + SR * SP2;
    const float* img_in  = inA ? g_imgA : g_imgB;
    float*       img_out = inA ? g_imgB : g_imgA;
    const int slice = blockIdx.z;
    const float* base = img_in + slice * HW;
    float* outp = img_out + slice * HW;
    float* skp  = g_skel + slice * HW;
    const int gx0 = blockIdx.x * TILE, gy0 = blockIdx.y * TILE;
    bool border = (gx0 < RAD) || (gy0 < RAD) ||
                  (gx0 + TILE + RAD > IMG_W) || (gy0 + TILE + RAD > IMG_H);
    if (border)
        morph2_body<INIT, true>(base, outp, skp, bufA, bufB);
    else
        morph2_body<INIT, false>(base, outp, skp, bufA, bufB);
}

// ---------------------------------------------------------------------------
// Endpoints + per-slice reductions:
// nsum = 3x3 sum of skel + 9*center (zero padding); ep = exp(-(nsum-11)^2)*skel
__global__ void __launch_bounds__(1024) endpoint_kernel() {
    __shared__ float s_sk[34][36];
    const int slice = blockIdx.z;
    const int gx0 = blockIdx.x * 32;
    const int gy0 = blockIdx.y * 32;
    const int t = threadIdx.y * 32 + threadIdx.x;
    const float* base = g_skel + slice * HW;

    for (int idx = t; idx < 34 * 34; idx += 1024) {
        int j = idx / 34, i = idx - j * 34;
        int gy = gy0 + j - 1, gx = gx0 + i - 1;
        float v = 0.0f;
        if ((unsigned)gy < IMG_H && (unsigned)gx < IMG_W)
            v = __ldg(base + gy * IMG_W + gx);
        s_sk[j][i] = v;
    }
    __syncthreads();

    const int ty = threadIdx.y, tx = threadIdx.x;
    float c = s_sk[ty + 1][tx + 1];
    float nsum = 9.0f * c;
    #pragma unroll
    for (int dj = 0; dj < 3; dj++)
        #pragma unroll
        for (int di = 0; di < 3; di++)
            nsum += s_sk[ty + dj][tx + di];
    float d = nsum - 11.0f;
    float ep = expf(-d * d) * c;

    double e  = (double)ep;
    double ey = (double)ep * (double)(gy0 + ty);
    double ex = (double)ep * (double)(gx0 + tx);

    __shared__ double red[32][3];
    unsigned lane = t & 31u, wid = t >> 5;
    #pragma unroll
    for (int o = 16; o > 0; o >>= 1) {
        e  += __shfl_down_sync(0xffffffffu, e, o);
        ey += __shfl_down_sync(0xffffffffu, ey, o);
        ex += __shfl_down_sync(0xffffffffu, ex, o);
    }
    if (lane == 0) { red[wid][0] = e; red[wid][1] = ey; red[wid][2] = ex; }
    __syncthreads();
    if (wid == 0) {
        e  = red[lane][0];
        ey = red[lane][1];
        ex = red[lane][2];
        #pragma unroll
        for (int o = 16; o > 0; o >>= 1) {
            e  += __shfl_down_sync(0xffffffffu, e, o);
            ey += __shfl_down_sync(0xffffffffu, ey, o);
            ex += __shfl_down_sync(0xffffffffu, ex, o);
        }
        if (lane == 0) {
            atomicAdd(&g_acc[slice * 3 + 0], e);
            atomicAdd(&g_acc[slice * 3 + 1], ey);
            atomicAdd(&g_acc[slice * 3 + 2], ex);
        }
    }
}

// ---------------------------------------------------------------------------
__global__ void final_kernel(float* out) {
    if (threadIdx.x == 0 && blockIdx.x == 0) {
        double dist = 0.0, cnt = 0.0;
        for (int b = 0; b < BATCH; b++) {
            double tp = g_acc[b * 3 + 0];
            double yp = g_acc[b * 3 + 1];
            double xp = g_acc[b * 3 + 2];
            double tt = g_acc[(BATCH + b) * 3 + 0];
            double yt = g_acc[(BATCH + b) * 3 + 1];
            double xt = g_acc[(BATCH + b) * 3 + 2];
            double ycp = yp / (tp + 1e-8), xcp = xp / (tp + 1e-8);
            double yct = yt / (tt + 1e-8), xct = xt / (tt + 1e-8);
            double dy = ycp - yct, dx = xcp - xct;
            dist += sqrt(dy * dy + dx * dx);
            cnt += fabs(tp - tt) / (tp + tt + 1e-8);
        }
        dist /= (double)BATCH;
        cnt  /= (double)BATCH;
        double diag = sqrt((double)IMG_H * IMG_H + (double)IMG_W * IMG_W);
        double distance_loss = dist / (diag * 1.0 /*TAU*/ + 1e-8);
        double ep_loss = distance_loss + 1.0 /*LAMBDA_COUNT*/ * cnt;
        double inter = g_acc[48], sp = g_acc[49], st = g_acc[50];
        double dice = 1.0 - (2.0 * inter + 1.0) / (st + sp + 1.0);
        out[0] = (float)(0.85 * dice + 0.15 * ep_loss);
    }
}

// ---------------------------------------------------------------------------
extern "C" void kernel_launch(void* const* d_in, const int* in_sizes, int n_in,
                              void* d_out, int out_size) {
    const float* net;
    const int* ytrue;
    if (in_sizes[0] == BATCH * 2 * HW) {
        net = (const float*)d_in[0];
        ytrue = (const int*)d_in[1];
    } else {
        net = (const float*)d_in[1];
        ytrue = (const int*)d_in[0];
    }
    float* out = (float*)d_out;

    // Allow >48KB dynamic smem (idempotent; not an allocation)
    cudaFuncSetAttribute(morph2_kernel<true>,
                         cudaFuncAttributeMaxDynamicSharedMemorySize, SMEM_BYTES);
    cudaFuncSetAttribute(morph2_kernel<false>,
                         cudaFuncAttributeMaxDynamicSharedMemorySize, SMEM_BYTES);

    zero_acc_kernel<<<1, 64>>>();
    init_kernel<<<dim3(HW / 1024, BATCH), 256>>>((const float4*)net,
                                                 (const int4*)ytrue);

    dim3 mgrid(IMG_W / TILE, IMG_H / TILE, NSLICE);

    // First fused kernel: initial skel + FUSE iterations (reads A, writes B)
    morph2_kernel<true><<<mgrid, 1024, SMEM_BYTES>>>(1);

    // Remaining (NUM_ITER - FUSE) iterations in chunks of FUSE, ping-ponging
    int inA = 0;
    for (int k = FUSE; k < NUM_ITER; k += FUSE) {
        morph2_kernel<false><<<mgrid, 1024, SMEM_BYTES>>>(inA);
        inA ^= 1;
    }

    dim3 grid(IMG_W / 32, IMG_H / 32, NSLICE);
    dim3 blk(32, 32);
    endpoint_kernel<<<grid, blk>>>();
    final_kernel<<<1, 1>>>(out);
}